// round 2
// baseline (speedup 1.0000x reference)
#include <cuda_runtime.h>

#define N_NODES 100000
#define N_EDGES 1600000
#define F_IN 64
#define HDIM 128
#define NB ((N_NODES + 1023) / 1024)

// ---------------- scratch (device globals: no allocation allowed) ----------
__device__ int   g_deg[N_NODES];
__device__ int   g_off[N_NODES + 1];
__device__ int   g_cur[N_NODES];
__device__ int   g_bsum[128];
__device__ int   g_boff[128];
__device__ int   g_csr[N_EDGES];
__device__ float g_mean1[N_NODES * F_IN];
__device__ float g_h[N_NODES * HDIM];
__device__ float g_mean2[N_NODES * HDIM];
__device__ float g_wcat1[128 * 128];   // [k][o]  k = [Wl1 | Wr1]
__device__ float g_wcat2[256 * 128];   // [k][o]  k = [Wl2 | Wr2]

// ---------------- CSR build ------------------------------------------------
__global__ void k_zero_deg() {
    int i = blockIdx.x * blockDim.x + threadIdx.x;
    if (i < N_NODES) g_deg[i] = 0;
}

__global__ void k_hist(const int* __restrict__ dst, int E) {
    int i = blockIdx.x * blockDim.x + threadIdx.x;
    if (i < E) atomicAdd(&g_deg[dst[i]], 1);
}

__global__ void k_blocksum() {
    __shared__ int sh[32];
    int i = blockIdx.x * 1024 + threadIdx.x;
    int v = (i < N_NODES) ? g_deg[i] : 0;
    #pragma unroll
    for (int d = 16; d > 0; d >>= 1) v += __shfl_down_sync(~0u, v, d);
    if ((threadIdx.x & 31) == 0) sh[threadIdx.x >> 5] = v;
    __syncthreads();
    if (threadIdx.x < 32) {
        int s = sh[threadIdx.x];
        #pragma unroll
        for (int d = 16; d > 0; d >>= 1) s += __shfl_down_sync(~0u, s, d);
        if (threadIdx.x == 0) g_bsum[blockIdx.x] = s;
    }
}

__global__ void k_scan_sums(int nb) {
    int lane = threadIdx.x;
    int carry = 0;
    for (int base = 0; base < nb; base += 32) {
        int i = base + lane;
        int orig = (i < nb) ? g_bsum[i] : 0;
        int v = orig;
        #pragma unroll
        for (int d = 1; d < 32; d <<= 1) {
            int t = __shfl_up_sync(~0u, v, d);
            if (lane >= d) v += t;
        }
        if (i < nb) g_boff[i] = carry + v - orig;
        carry += __shfl_sync(~0u, v, 31);
    }
}

__global__ void k_offsets() {
    __shared__ int sh[32];
    int tid = threadIdx.x;
    int lane = tid & 31, wid = tid >> 5;
    int i = blockIdx.x * 1024 + tid;
    int orig = (i < N_NODES) ? g_deg[i] : 0;
    int v = orig;
    #pragma unroll
    for (int d = 1; d < 32; d <<= 1) {
        int t = __shfl_up_sync(~0u, v, d);
        if (lane >= d) v += t;
    }
    if (lane == 31) sh[wid] = v;
    __syncthreads();
    if (wid == 0) {
        int s = sh[lane];
        #pragma unroll
        for (int d = 1; d < 32; d <<= 1) {
            int t = __shfl_up_sync(~0u, s, d);
            if (lane >= d) s += t;
        }
        sh[lane] = s;
    }
    __syncthreads();
    int base = g_boff[blockIdx.x] + (wid ? sh[wid - 1] : 0);
    int excl = base + v - orig;
    if (i < N_NODES) {
        g_off[i] = excl;
        g_cur[i] = excl;
        if (i == N_NODES - 1) g_off[N_NODES] = excl + orig;
    }
}

__global__ void k_scatter(const int* __restrict__ src, const int* __restrict__ dst, int E) {
    int i = blockIdx.x * blockDim.x + threadIdx.x;
    if (i < E) {
        int p = atomicAdd(&g_cur[dst[i]], 1);
        g_csr[p] = src[i];
    }
}

// ---------------- weight transpose ----------------------------------------
__global__ void k_wcat(const float* __restrict__ Wl1, const float* __restrict__ Wr1,
                       const float* __restrict__ Wl2, const float* __restrict__ Wr2) {
    int i = blockIdx.x * blockDim.x + threadIdx.x;
    if (i < 128 * 128) {
        int k = i >> 7, o = i & 127;
        g_wcat1[i] = (k < 64) ? Wl1[o * 64 + k] : Wr1[o * 64 + (k - 64)];
    }
    if (i < 256 * 128) {
        int k = i >> 7, o = i & 127;
        g_wcat2[i] = (k < 128) ? Wl2[o * 128 + k] : Wr2[o * 128 + (k - 128)];
    }
}

// ---------------- aggregation (one warp per node) ---------------------------
__global__ void k_agg1(const float* __restrict__ x) {
    int w = (blockIdx.x * blockDim.x + threadIdx.x) >> 5;
    int lane = threadIdx.x & 31;
    if (w >= N_NODES) return;
    int beg = g_off[w], end = g_off[w + 1];
    const float2* __restrict__ xr = (const float2*)x;   // row = 32 float2
    float ax = 0.f, ay = 0.f;
    for (int base = beg; base < end; base += 32) {
        int j = base + lane;
        int s_l = (j < end) ? g_csr[j] : 0;
        int cnt = min(32, end - base);
        for (int t = 0; t < cnt; t++) {
            int s = __shfl_sync(~0u, s_l, t);
            float2 v = xr[s * 32 + lane];
            ax += v.x; ay += v.y;
        }
    }
    float inv = 1.f / fmaxf((float)(end - beg), 1.f);
    float2 o; o.x = ax * inv; o.y = ay * inv;
    ((float2*)g_mean1)[w * 32 + lane] = o;
}

__global__ void k_agg2() {
    int w = (blockIdx.x * blockDim.x + threadIdx.x) >> 5;
    int lane = threadIdx.x & 31;
    if (w >= N_NODES) return;
    int beg = g_off[w], end = g_off[w + 1];
    const float4* __restrict__ hr = (const float4*)g_h;  // row = 32 float4
    float a0 = 0.f, a1 = 0.f, a2 = 0.f, a3 = 0.f;
    for (int base = beg; base < end; base += 32) {
        int j = base + lane;
        int s_l = (j < end) ? g_csr[j] : 0;
        int cnt = min(32, end - base);
        for (int t = 0; t < cnt; t++) {
            int s = __shfl_sync(~0u, s_l, t);
            float4 v = hr[s * 32 + lane];
            a0 += v.x; a1 += v.y; a2 += v.z; a3 += v.w;
        }
    }
    float inv = 1.f / fmaxf((float)(end - beg), 1.f);
    float4 o; o.x = a0 * inv; o.y = a1 * inv; o.z = a2 * inv; o.w = a3 * inv;
    ((float4*)g_mean2)[w * 32 + lane] = o;
}

// ---------------- fused GEMM: C = [A1|A2] @ W + bias (opt. ReLU) ------------
// W is [K1+K2][128] (k-major). BM=64, BN=128, BK=16, 256 threads,
// per-thread micro-tile 8 rows x 4 cols.
template<int K1, int K2, bool RELU>
__global__ void __launch_bounds__(256) k_gemm(
    const float* __restrict__ A1, const float* __restrict__ A2,
    const float* __restrict__ W, const float* __restrict__ bias,
    float* __restrict__ C)
{
    constexpr int K = K1 + K2;
    constexpr int BM = 64, BN = 128, BK = 16;
    __shared__ __align__(16) float As[BK][68];   // padded: 2-way STS conflict max
    __shared__ __align__(16) float Bs[BK][BN];

    int tid = threadIdx.x;
    int tr = tid >> 5;       // 0..7  -> rows tr*8 .. tr*8+7
    int tc = tid & 31;       // 0..31 -> cols tc*4 .. tc*4+3
    int rowBase = blockIdx.x * BM;

    float acc[8][4];
    #pragma unroll
    for (int r = 0; r < 8; r++)
        #pragma unroll
        for (int c = 0; c < 4; c++) acc[r][c] = 0.f;

    for (int k0 = 0; k0 < K; k0 += BK) {
        // A tile: 64 rows x 16 k (coalesced 64B per 16 threads)
        #pragma unroll
        for (int i = 0; i < 4; i++) {
            int lin = tid + i * 256;
            int m = lin >> 4, k = lin & 15;
            int row = rowBase + m, gk = k0 + k;
            float v = 0.f;
            if (row < N_NODES)
                v = (gk < K1) ? A1[row * K1 + gk] : A2[row * K2 + (gk - K1)];
            As[k][m] = v;
        }
        // B tile: 16 k x 128 o (fully coalesced)
        #pragma unroll
        for (int i = 0; i < 8; i++) {
            int lin = tid + i * 256;
            int o = lin & 127, k = lin >> 7;
            Bs[k][o] = W[(k0 + k) * 128 + o];
        }
        __syncthreads();
        #pragma unroll
        for (int kk = 0; kk < BK; kk++) {
            float4 a0 = *(const float4*)&As[kk][tr * 8];
            float4 a1 = *(const float4*)&As[kk][tr * 8 + 4];
            float4 b  = *(const float4*)&Bs[kk][tc * 4];
            float av[8] = {a0.x, a0.y, a0.z, a0.w, a1.x, a1.y, a1.z, a1.w};
            float bv[4] = {b.x, b.y, b.z, b.w};
            #pragma unroll
            for (int r = 0; r < 8; r++)
                #pragma unroll
                for (int c = 0; c < 4; c++)
                    acc[r][c] += av[r] * bv[c];
        }
        __syncthreads();
    }

    int ocol = tc * 4;
    float4 bv = *(const float4*)&bias[ocol];
    #pragma unroll
    for (int r = 0; r < 8; r++) {
        int row = rowBase + tr * 8 + r;
        if (row < N_NODES) {
            float4 o;
            o.x = acc[r][0] + bv.x;
            o.y = acc[r][1] + bv.y;
            o.z = acc[r][2] + bv.z;
            o.w = acc[r][3] + bv.w;
            if (RELU) {
                o.x = fmaxf(o.x, 0.f); o.y = fmaxf(o.y, 0.f);
                o.z = fmaxf(o.z, 0.f); o.w = fmaxf(o.w, 0.f);
            }
            *(float4*)&C[row * 128 + ocol] = o;
        }
    }
}

// ---------------- launch ----------------------------------------------------
extern "C" void kernel_launch(void* const* d_in, const int* in_sizes, int n_in,
                              void* d_out, int out_size) {
    const float* x   = (const float*)d_in[0];
    const int*   ei  = (const int*)d_in[1];
    const float* Wl1 = (const float*)d_in[2];
    const float* bl1 = (const float*)d_in[3];
    const float* Wr1 = (const float*)d_in[4];
    const float* Wl2 = (const float*)d_in[5];
    const float* bl2 = (const float*)d_in[6];
    const float* Wr2 = (const float*)d_in[7];
    float* out = (float*)d_out;

    int E = in_sizes[1] / 2;
    const int* src = ei;
    const int* dst = ei + E;

    float *mean1, *hbuf, *mean2, *wcat1, *wcat2;
    cudaGetSymbolAddress((void**)&mean1, g_mean1);
    cudaGetSymbolAddress((void**)&hbuf,  g_h);
    cudaGetSymbolAddress((void**)&mean2, g_mean2);
    cudaGetSymbolAddress((void**)&wcat1, g_wcat1);
    cudaGetSymbolAddress((void**)&wcat2, g_wcat2);

    k_zero_deg<<<(N_NODES + 255) / 256, 256>>>();
    k_hist<<<(E + 255) / 256, 256>>>(dst, E);
    k_blocksum<<<NB, 1024>>>();
    k_scan_sums<<<1, 32>>>(NB);
    k_offsets<<<NB, 1024>>>();
    k_scatter<<<(E + 255) / 256, 256>>>(src, dst, E);
    k_wcat<<<(256 * 128 + 255) / 256, 256>>>(Wl1, Wr1, Wl2, Wr2);

    k_agg1<<<(N_NODES * 32 + 255) / 256, 256>>>(x);
    k_gemm<64, 64, true><<<(N_NODES + 63) / 64, 256>>>(mean1, x, wcat1, bl1, hbuf);
    k_agg2<<<(N_NODES * 32 + 255) / 256, 256>>>();
    k_gemm<128, 128, false><<<(N_NODES + 63) / 64, 256>>>(mean2, hbuf, wcat2, bl2, out);
}

// round 5
// speedup vs baseline: 1.5405x; 1.5405x over previous
#include <cuda_runtime.h>
#include <cuda_bf16.h>
#include <cstdint>

#define N_NODES 100000
#define N_EDGES 1600000
#define NB ((N_NODES + 1023) / 1024)
#define MTILES ((N_NODES + 127) / 128)

// ======================= PTX helpers (arch-agnostic, sm_80+) ================
__device__ __forceinline__ uint32_t smem_u32(const void* p) {
    uint32_t a;
    asm("{ .reg .u64 t; cvta.to.shared.u64 t, %1; cvt.u32.u64 %0, t; }" : "=r"(a) : "l"(p));
    return a;
}
__device__ __forceinline__ void ldsm_x4(uint32_t* r, uint32_t addr) {
    asm volatile("ldmatrix.sync.aligned.m8n8.x4.shared.b16 {%0,%1,%2,%3}, [%4];"
        : "=r"(r[0]), "=r"(r[1]), "=r"(r[2]), "=r"(r[3]) : "r"(addr));
}
__device__ __forceinline__ void mma_bf16(float* c, const uint32_t* a, uint32_t b0, uint32_t b1) {
    asm volatile("mma.sync.aligned.m16n8k16.row.col.f32.bf16.bf16.f32 "
        "{%0,%1,%2,%3}, {%4,%5,%6,%7}, {%8,%9}, {%0,%1,%2,%3};"
        : "+f"(c[0]), "+f"(c[1]), "+f"(c[2]), "+f"(c[3])
        : "r"(a[0]), "r"(a[1]), "r"(a[2]), "r"(a[3]), "r"(b0), "r"(b1));
}
__device__ __forceinline__ void cp16(uint32_t dst, const void* src, int srcbytes) {
    asm volatile("cp.async.cg.shared.global [%0], [%1], 16, %2;"
                 :: "r"(dst), "l"(src), "r"(srcbytes));
}
#define CP_COMMIT() asm volatile("cp.async.commit_group;" ::: "memory")
#define CP_WAIT(n)  asm volatile("cp.async.wait_group %0;" :: "n"(n) : "memory")

// ======================= scratch globals ====================================
__device__ int g_deg[N_NODES];
__device__ int g_off[N_NODES + 1];
__device__ int g_cur[N_NODES];
__device__ int g_bsum[128];
__device__ int g_boff[128];
__device__ int g_csr[N_EDGES];
// A planes: layer1 [N][128] (cols 0-63 mean1, 64-127 x), layer2 [N][256] (0-127 mean2, 128-255 h)
__device__ __nv_bfloat16 g_a1hi[(size_t)N_NODES * 128];
__device__ __nv_bfloat16 g_a1lo[(size_t)N_NODES * 128];
__device__ __nv_bfloat16 g_a2hi[(size_t)N_NODES * 256];
__device__ __nv_bfloat16 g_a2lo[(size_t)N_NODES * 256];
// weights k-contiguous per output row: w1 [n=128][k=128], w2 [n=128][k=256]
__device__ __nv_bfloat16 g_w1hi[128 * 128], g_w1lo[128 * 128];
__device__ __nv_bfloat16 g_w2hi[128 * 256], g_w2lo[128 * 256];

__device__ __forceinline__ void f32split(float v, __nv_bfloat16& hi, __nv_bfloat16& lo) {
    hi = __float2bfloat16(v);
    lo = __float2bfloat16(v - __bfloat162float(hi));
}

// ======================= CSR build ==========================================
__global__ void k_zero_deg() {
    int i = blockIdx.x * blockDim.x + threadIdx.x;
    if (i < N_NODES) g_deg[i] = 0;
}
__global__ void k_hist(const int* __restrict__ dst, int E) {
    int i = blockIdx.x * blockDim.x + threadIdx.x;
    if (i < E) atomicAdd(&g_deg[dst[i]], 1);
}
__global__ void k_blocksum() {
    __shared__ int sh[32];
    int i = blockIdx.x * 1024 + threadIdx.x;
    int v = (i < N_NODES) ? g_deg[i] : 0;
    #pragma unroll
    for (int d = 16; d > 0; d >>= 1) v += __shfl_down_sync(~0u, v, d);
    if ((threadIdx.x & 31) == 0) sh[threadIdx.x >> 5] = v;
    __syncthreads();
    if (threadIdx.x < 32) {
        int s = sh[threadIdx.x];
        #pragma unroll
        for (int d = 16; d > 0; d >>= 1) s += __shfl_down_sync(~0u, s, d);
        if (threadIdx.x == 0) g_bsum[blockIdx.x] = s;
    }
}
__global__ void k_scan_sums(int nb) {
    int lane = threadIdx.x;
    int carry = 0;
    for (int base = 0; base < nb; base += 32) {
        int i = base + lane;
        int orig = (i < nb) ? g_bsum[i] : 0;
        int v = orig;
        #pragma unroll
        for (int d = 1; d < 32; d <<= 1) {
            int t = __shfl_up_sync(~0u, v, d);
            if (lane >= d) v += t;
        }
        if (i < nb) g_boff[i] = carry + v - orig;
        carry += __shfl_sync(~0u, v, 31);
    }
}
__global__ void k_offsets() {
    __shared__ int sh[32];
    int tid = threadIdx.x;
    int lane = tid & 31, wid = tid >> 5;
    int i = blockIdx.x * 1024 + tid;
    int orig = (i < N_NODES) ? g_deg[i] : 0;
    int v = orig;
    #pragma unroll
    for (int d = 1; d < 32; d <<= 1) {
        int t = __shfl_up_sync(~0u, v, d);
        if (lane >= d) v += t;
    }
    if (lane == 31) sh[wid] = v;
    __syncthreads();
    if (wid == 0) {
        int s = sh[lane];
        #pragma unroll
        for (int d = 1; d < 32; d <<= 1) {
            int t = __shfl_up_sync(~0u, s, d);
            if (lane >= d) s += t;
        }
        sh[lane] = s;
    }
    __syncthreads();
    int base = g_boff[blockIdx.x] + (wid ? sh[wid - 1] : 0);
    int excl = base + v - orig;
    if (i < N_NODES) {
        g_off[i] = excl;
        g_cur[i] = excl;
        if (i == N_NODES - 1) g_off[N_NODES] = excl + orig;
    }
}
__global__ void k_scatter(const int* __restrict__ src, const int* __restrict__ dst, int E) {
    int i = blockIdx.x * blockDim.x + threadIdx.x;
    if (i < E) {
        int p = atomicAdd(&g_cur[dst[i]], 1);
        g_csr[p] = src[i];
    }
}

// ======================= prep: split x and W into bf16 hi/lo ================
__global__ void k_xsplit(const float* __restrict__ x) {
    int i = blockIdx.x * blockDim.x + threadIdx.x;   // pair index over N*32
    if (i >= N_NODES * 32) return;
    int node = i >> 5, kp = i & 31;
    float2 v = ((const float2*)x)[i];
    __nv_bfloat162 hi, lo;
    f32split(v.x, hi.x, lo.x);
    f32split(v.y, hi.y, lo.y);
    size_t off = (size_t)node * 128 + 64 + kp * 2;
    *(__nv_bfloat162*)(g_a1hi + off) = hi;
    *(__nv_bfloat162*)(g_a1lo + off) = lo;
}
__global__ void k_wprep(const float* __restrict__ Wl1, const float* __restrict__ Wr1,
                        const float* __restrict__ Wl2, const float* __restrict__ Wr2) {
    int i = blockIdx.x * blockDim.x + threadIdx.x;
    if (i < 128 * 128) {
        int n = i >> 7, k = i & 127;
        float v = (k < 64) ? Wl1[n * 64 + k] : Wr1[n * 64 + (k - 64)];
        f32split(v, g_w1hi[i], g_w1lo[i]);
    }
    if (i < 128 * 256) {
        int n = i >> 8, k = i & 255;
        float v = (k < 128) ? Wl2[n * 128 + k] : Wr2[n * 128 + (k - 128)];
        f32split(v, g_w2hi[i], g_w2lo[i]);
    }
}

// ======================= aggregation (one warp per node) ====================
__global__ void k_agg1(const float* __restrict__ x) {
    int w = (blockIdx.x * blockDim.x + threadIdx.x) >> 5;
    int lane = threadIdx.x & 31;
    if (w >= N_NODES) return;
    int beg = g_off[w], end = g_off[w + 1];
    const float2* __restrict__ xr = (const float2*)x;
    float ax = 0.f, ay = 0.f;
    for (int base = beg; base < end; base += 32) {
        int j = base + lane;
        int s_l = (j < end) ? g_csr[j] : 0;
        int cnt = min(32, end - base);
        for (int t = 0; t < cnt; t++) {
            int s = __shfl_sync(~0u, s_l, t);
            float2 v = xr[s * 32 + lane];
            ax += v.x; ay += v.y;
        }
    }
    float inv = 1.f / fmaxf((float)(end - beg), 1.f);
    __nv_bfloat162 hi, lo;
    f32split(ax * inv, hi.x, lo.x);
    f32split(ay * inv, hi.y, lo.y);
    ((__nv_bfloat162*)(g_a1hi + (size_t)w * 128))[lane] = hi;
    ((__nv_bfloat162*)(g_a1lo + (size_t)w * 128))[lane] = lo;
}
__global__ void k_agg2() {
    int w = (blockIdx.x * blockDim.x + threadIdx.x) >> 5;
    int lane = threadIdx.x & 31;
    if (w >= N_NODES) return;
    int beg = g_off[w], end = g_off[w + 1];
    float a0 = 0.f, a1 = 0.f, a2 = 0.f, a3 = 0.f;
    for (int base = beg; base < end; base += 32) {
        int j = base + lane;
        int s_l = (j < end) ? g_csr[j] : 0;
        int cnt = min(32, end - base);
        for (int t = 0; t < cnt; t++) {
            int s = __shfl_sync(~0u, s_l, t);
            const __nv_bfloat162* ph = (const __nv_bfloat162*)(g_a2hi + (size_t)s * 256 + 128);
            const __nv_bfloat162* pl = (const __nv_bfloat162*)(g_a2lo + (size_t)s * 256 + 128);
            __nv_bfloat162 h0 = ph[lane * 2], h1 = ph[lane * 2 + 1];
            __nv_bfloat162 l0 = pl[lane * 2], l1 = pl[lane * 2 + 1];
            a0 += __bfloat162float(h0.x) + __bfloat162float(l0.x);
            a1 += __bfloat162float(h0.y) + __bfloat162float(l0.y);
            a2 += __bfloat162float(h1.x) + __bfloat162float(l1.x);
            a3 += __bfloat162float(h1.y) + __bfloat162float(l1.y);
        }
    }
    float inv = 1.f / fmaxf((float)(end - beg), 1.f);
    __nv_bfloat162 hA, lA, hB, lB;
    f32split(a0 * inv, hA.x, lA.x);
    f32split(a1 * inv, hA.y, lA.y);
    f32split(a2 * inv, hB.x, lB.x);
    f32split(a3 * inv, hB.y, lB.y);
    __nv_bfloat162* oh = (__nv_bfloat162*)(g_a2hi + (size_t)w * 256);
    __nv_bfloat162* ol = (__nv_bfloat162*)(g_a2lo + (size_t)w * 256);
    oh[lane * 2] = hA; oh[lane * 2 + 1] = hB;
    ol[lane * 2] = lA; ol[lane * 2 + 1] = lB;
}

// ======================= mma.sync bf16x3 GEMM ===============================
// C[128 tile, 128] = A[128, KTOT] * W^T (W stored [n][k] k-contig).
// 8 warps: warpM = wid&3 (32 rows each), warpN = wid>>2 (64 cols each).
// BK=64 chunks; SMEM buffer = 4 planes (Ahi, Alo, Whi, Wlo) x 128 rows x 64 bf16,
// XOR swizzle: seg' = seg ^ (row&7), 16B segs. Double-buffered cp.async.
#define PLANE_BYTES 16384
#define BUF_BYTES   65536
#define GEMM_SMEM  (2 * BUF_BYTES)

template <int KTOT>
__device__ __forceinline__ void load_chunk(
    uint32_t sbuf, const __nv_bfloat16* __restrict__ Ahi,
    const __nv_bfloat16* __restrict__ Alo, const __nv_bfloat16* __restrict__ Whi,
    const __nv_bfloat16* __restrict__ Wlo, int rowBase, int c, int tid)
{
    const __nv_bfloat16* planes[4] = {Ahi, Alo, Whi, Wlo};
    #pragma unroll
    for (int i = 0; i < 16; i++) {
        int idx = i * 256 + tid;
        int plane = idx >> 10, rem = idx & 1023;
        int row = rem >> 3, seg = rem & 7;
        uint32_t dst = sbuf + plane * PLANE_BYTES + row * 128 + ((seg ^ (row & 7)) << 4);
        int bytes = 16;
        const __nv_bfloat16* srcp;
        if (plane < 2) {
            int node = rowBase + row;
            if (node >= N_NODES) { node = N_NODES - 1; bytes = 0; }
            srcp = planes[plane] + (size_t)node * KTOT + c * 64 + seg * 8;
        } else {
            srcp = planes[plane] + (size_t)row * KTOT + c * 64 + seg * 8;
        }
        cp16(dst, srcp, bytes);
    }
}

template <int KTOT, bool LAYER1>
__global__ void __launch_bounds__(256, 1)
k_mmagemm(const __nv_bfloat16* __restrict__ Ahi, const __nv_bfloat16* __restrict__ Alo,
          const __nv_bfloat16* __restrict__ Whi, const __nv_bfloat16* __restrict__ Wlo,
          const float* __restrict__ bias, float* __restrict__ out) {
    extern __shared__ char smem[];
    uint32_t sbase = smem_u32(smem);
    int tid = threadIdx.x;
    int wid = tid >> 5, lane = tid & 31;
    int warpM = wid & 3, warpN = wid >> 2;
    int rowBase = blockIdx.x * 128;
    constexpr int NCHUNK = KTOT / 64;

    float acc[2][8][4];
    #pragma unroll
    for (int a = 0; a < 2; a++)
        #pragma unroll
        for (int b = 0; b < 8; b++)
            #pragma unroll
            for (int d = 0; d < 4; d++) acc[a][b][d] = 0.f;

    load_chunk<KTOT>(sbase, Ahi, Alo, Whi, Wlo, rowBase, 0, tid);
    CP_COMMIT();

    for (int c = 0; c < NCHUNK; c++) {
        if (c + 1 < NCHUNK) {
            load_chunk<KTOT>(sbase + ((c + 1) & 1) * BUF_BYTES, Ahi, Alo, Whi, Wlo,
                             rowBase, c + 1, tid);
            CP_COMMIT();
            CP_WAIT(1);
        } else {
            CP_WAIT(0);
        }
        __syncthreads();

        uint32_t sb = sbase + (c & 1) * BUF_BYTES;
        uint32_t sAh = sb, sAl = sb + PLANE_BYTES;
        uint32_t sBh = sb + 2 * PLANE_BYTES, sBl = sb + 3 * PLANE_BYTES;

        #pragma unroll
        for (int ks = 0; ks < 4; ks++) {
            uint32_t aH[2][4], aL[2][4];
            #pragma unroll
            for (int tm = 0; tm < 2; tm++) {
                int row = warpM * 32 + tm * 16 + (lane & 15);
                int seg = ks * 2 + (lane >> 4);
                uint32_t off = row * 128 + ((seg ^ (row & 7)) << 4);
                ldsm_x4(aH[tm], sAh + off);
                ldsm_x4(aL[tm], sAl + off);
            }
            #pragma unroll
            for (int tp = 0; tp < 4; tp++) {
                int n = warpN * 64 + tp * 16 + (lane & 7) + (((lane >> 4) & 1) << 3);
                int seg = ks * 2 + ((lane >> 3) & 1);
                uint32_t boff = n * 128 + ((seg ^ (n & 7)) << 4);
                uint32_t bh[4];
                ldsm_x4(bh, sBh + boff);
                #pragma unroll
                for (int tm = 0; tm < 2; tm++) {
                    mma_bf16(acc[tm][tp * 2],     aH[tm], bh[0], bh[1]);
                    mma_bf16(acc[tm][tp * 2 + 1], aH[tm], bh[2], bh[3]);
                    mma_bf16(acc[tm][tp * 2],     aL[tm], bh[0], bh[1]);
                    mma_bf16(acc[tm][tp * 2 + 1], aL[tm], bh[2], bh[3]);
                }
                uint32_t bl[4];
                ldsm_x4(bl, sBl + boff);
                #pragma unroll
                for (int tm = 0; tm < 2; tm++) {
                    mma_bf16(acc[tm][tp * 2],     aH[tm], bl[0], bl[1]);
                    mma_bf16(acc[tm][tp * 2 + 1], aH[tm], bl[2], bl[3]);
                }
            }
        }
        __syncthreads();
    }

    // epilogue
    #pragma unroll
    for (int tm = 0; tm < 2; tm++) {
        #pragma unroll
        for (int tn = 0; tn < 8; tn++) {
            int col = warpN * 64 + tn * 8 + 2 * (lane & 3);
            float2 bv = *(const float2*)(bias + col);
            #pragma unroll
            for (int half = 0; half < 2; half++) {
                int m = rowBase + warpM * 32 + tm * 16 + (lane >> 2) + half * 8;
                if (m >= N_NODES) continue;
                float v0 = acc[tm][tn][half * 2]     + bv.x;
                float v1 = acc[tm][tn][half * 2 + 1] + bv.y;
                if (LAYER1) {
                    v0 = fmaxf(v0, 0.f);
                    v1 = fmaxf(v1, 0.f);
                    __nv_bfloat162 hi, lo;
                    f32split(v0, hi.x, lo.x);
                    f32split(v1, hi.y, lo.y);
                    *(__nv_bfloat162*)(g_a2hi + (size_t)m * 256 + 128 + col) = hi;
                    *(__nv_bfloat162*)(g_a2lo + (size_t)m * 256 + 128 + col) = lo;
                } else {
                    float2 o; o.x = v0; o.y = v1;
                    *(float2*)(out + (size_t)m * 128 + col) = o;
                }
            }
        }
    }
}

// ======================= launch =============================================
extern "C" void kernel_launch(void* const* d_in, const int* in_sizes, int n_in,
                              void* d_out, int out_size) {
    const float* x   = (const float*)d_in[0];
    const int*   ei  = (const int*)d_in[1];
    const float* Wl1 = (const float*)d_in[2];
    const float* bl1 = (const float*)d_in[3];
    const float* Wr1 = (const float*)d_in[4];
    const float* Wl2 = (const float*)d_in[5];
    const float* bl2 = (const float*)d_in[6];
    const float* Wr2 = (const float*)d_in[7];
    float* out = (float*)d_out;

    int E = in_sizes[1] / 2;
    const int* src = ei;
    const int* dst = ei + E;

    __nv_bfloat16 *a1hi, *a1lo, *a2hi, *a2lo, *w1hi, *w1lo, *w2hi, *w2lo;
    cudaGetSymbolAddress((void**)&a1hi, g_a1hi);
    cudaGetSymbolAddress((void**)&a1lo, g_a1lo);
    cudaGetSymbolAddress((void**)&a2hi, g_a2hi);
    cudaGetSymbolAddress((void**)&a2lo, g_a2lo);
    cudaGetSymbolAddress((void**)&w1hi, g_w1hi);
    cudaGetSymbolAddress((void**)&w1lo, g_w1lo);
    cudaGetSymbolAddress((void**)&w2hi, g_w2hi);
    cudaGetSymbolAddress((void**)&w2lo, g_w2lo);

    cudaFuncSetAttribute((const void*)k_mmagemm<128, true>,
                         cudaFuncAttributeMaxDynamicSharedMemorySize, GEMM_SMEM);
    cudaFuncSetAttribute((const void*)k_mmagemm<256, false>,
                         cudaFuncAttributeMaxDynamicSharedMemorySize, GEMM_SMEM);

    // CSR build
    k_zero_deg<<<(N_NODES + 255) / 256, 256>>>();
    k_hist<<<(E + 255) / 256, 256>>>(dst, E);
    k_blocksum<<<NB, 1024>>>();
    k_scan_sums<<<1, 32>>>(NB);
    k_offsets<<<NB, 1024>>>();
    k_scatter<<<(E + 255) / 256, 256>>>(src, dst, E);

    // operand prep
    k_wprep<<<(128 * 256 + 255) / 256, 256>>>(Wl1, Wr1, Wl2, Wr2);
    k_xsplit<<<(N_NODES * 32 + 255) / 256, 256>>>(x);

    // layer 1
    k_agg1<<<(N_NODES * 32 + 255) / 256, 256>>>(x);
    k_mmagemm<128, true><<<MTILES, 256, GEMM_SMEM>>>(a1hi, a1lo, w1hi, w1lo, bl1, nullptr);

    // layer 2
    k_agg2<<<(N_NODES * 32 + 255) / 256, 256>>>();
    k_mmagemm<256, false><<<MTILES, 256, GEMM_SMEM>>>(a2hi, a2lo, w2hi, w2lo, bl2, out);
}